// round 5
// baseline (speedup 1.0000x reference)
#include <cuda_runtime.h>
#include <cuda_bf16.h>
#include <math.h>
#include <stdint.h>

// ---------------------------------------------------------------------------
// CosformerAttention: bsz=2, L=1024, E=512, H=8, D=64
// Flat row-major view: X[2048][512], row r = l*2 + b  (pure reshape in ref).
//   1) mma_qkv : Q=relu(X Wq^T+bq), K=relu(X Wk^T+bk), V=X Wv^T+bv  [HMMA bf16]
//   2) chunksum: per 128-chunk  KV_c[128][64] = sum k_exp (x) v ; z_c
//   3) scan    : exclusive prefix over the 8 chunks of each sequence
//   4) chunkattn: all-MMA: accW=(Q K^T)*cosdiff masked; out = W Vext + cross
//   5) mma_out : out = attn Wo^T + bo                               [HMMA bf16]
// All tensor work: split-bf16 (hi+lo, 3 products) mma.sync m16n8k16, fp32 acc.
// ---------------------------------------------------------------------------

constexpr int E_DIM  = 512;
constexpr int NROWS  = 2048;   // L * bsz
constexpr int CHUNK  = 128;
constexpr int NCHUNK = 128;    // 16 sequences * 8 chunks
constexpr float ANG  = 1.5707963267948966f / 1024.0f;  // (pi/2)/L
constexpr float EPSV = 1e-6f;

// scratch (device globals: allocation-free rule)
__device__ __align__(16) float g_QKV[NROWS * 1536];        // [2048][1536]: Q|K|V
__device__ __align__(16) float g_attn[NROWS * E_DIM];      // [2048][512]
__device__ __align__(16) float g_state[NCHUNK * 128 * 64]; // per-chunk KV state
__device__ __align__(16) float g_z[NCHUNK * 128];          // per-chunk k-sum

// ---------------------------------------------------------------------------
// helpers
// ---------------------------------------------------------------------------
__device__ __forceinline__ uint32_t smem_u32(const void* p) {
    uint32_t a;
    asm("{ .reg .u64 t; cvta.to.shared.u64 t, %1; cvt.u32.u64 %0, t; }"
        : "=r"(a) : "l"(p));
    return a;
}

__device__ __forceinline__ void ldsm_x4(uint32_t& r0, uint32_t& r1,
                                        uint32_t& r2, uint32_t& r3, uint32_t a) {
    asm volatile("ldmatrix.sync.aligned.m8n8.x4.shared.b16 {%0,%1,%2,%3}, [%4];"
                 : "=r"(r0), "=r"(r1), "=r"(r2), "=r"(r3) : "r"(a));
}
__device__ __forceinline__ void ldsm_x4_t(uint32_t& r0, uint32_t& r1,
                                          uint32_t& r2, uint32_t& r3, uint32_t a) {
    asm volatile("ldmatrix.sync.aligned.m8n8.x4.trans.shared.b16 {%0,%1,%2,%3}, [%4];"
                 : "=r"(r0), "=r"(r1), "=r"(r2), "=r"(r3) : "r"(a));
}

__device__ __forceinline__ void mma_bf16(float* c, const uint32_t* a,
                                         uint32_t b0, uint32_t b1) {
    asm volatile(
        "mma.sync.aligned.m16n8k16.row.col.f32.bf16.bf16.f32 "
        "{%0,%1,%2,%3}, {%4,%5,%6,%7}, {%8,%9}, {%0,%1,%2,%3};"
        : "+f"(c[0]), "+f"(c[1]), "+f"(c[2]), "+f"(c[3])
        : "r"(a[0]), "r"(a[1]), "r"(a[2]), "r"(a[3]), "r"(b0), "r"(b1));
}

// split (x0,x1) into packed bf16 hi pair (returned) and lo pair (out)
__device__ __forceinline__ uint32_t split2(float x0, float x1, uint32_t& lo) {
    uint32_t hi;
    asm("cvt.rn.bf16x2.f32 %0, %1, %2;" : "=r"(hi) : "f"(x1), "f"(x0));
    float h0 = __uint_as_float(hi << 16);
    float h1 = __uint_as_float(hi & 0xFFFF0000u);
    asm("cvt.rn.bf16x2.f32 %0, %1, %2;" : "=r"(lo) : "f"(x1 - h1), "f"(x0 - h0));
    return hi;
}

// ---------------------------------------------------------------------------
// HMMA split-bf16 GEMM tile: C[128x128] = A[128x512] * W[row0..+128][512]^T + b
// ---------------------------------------------------------------------------
constexpr int SROW    = 72;                     // halves per smem row
constexpr int ARR_B   = 128 * SROW * 2;         // 18432 bytes per array
constexpr int OFF_AH  = 0;
constexpr int OFF_AL  = ARR_B;
constexpr int OFF_WH  = 2 * ARR_B;
constexpr int OFF_WL  = 3 * ARR_B;
constexpr int STAGE_B = 4 * ARR_B;              // 73728
constexpr int TC_SMEM = 2 * STAGE_B;            // 147456

__device__ void tc_gemm_tile(const float* __restrict__ A, const float* __restrict__ W,
                             const float* __restrict__ bias, float* __restrict__ C,
                             int ldc, int m0, int nr0, int ccol0, bool relu)
{
    extern __shared__ char dynsm[];
    const uint32_t sbase = smem_u32(dynsm);
    const int tid  = threadIdx.x;
    const int wid  = tid >> 5, lane = tid & 31;
    const int wm   = (wid & 1) * 64;     // warp row offset in tile
    const int wn   = (wid >> 1) * 32;    // warp col offset in tile

    const float* Abase = A + (size_t)m0 * E_DIM;
    const float* Bbase = W + (size_t)nr0 * E_DIM;

    auto fill = [&](int st, int k0) {
        char* sb = dynsm + st * STAGE_B;
#pragma unroll
        for (int i = 0; i < 8; i++) {
            int idx = tid + i * 256;           // 0..2047
            int row = idx >> 4;                // 0..127
            int col = (idx & 15) * 4;          // 0..60 (halves/floats)
            float4 a = *(const float4*)(Abase + (size_t)row * E_DIM + k0 + col);
            float4 w = *(const float4*)(Bbase + (size_t)row * E_DIM + k0 + col);
            uint32_t off = (uint32_t)(row * SROW + col) * 2;   // byte offset
            uint32_t l0, l1, h0, h1;
            h0 = split2(a.x, a.y, l0); h1 = split2(a.z, a.w, l1);
            *(uint2*)(sb + OFF_AH + off) = make_uint2(h0, h1);
            *(uint2*)(sb + OFF_AL + off) = make_uint2(l0, l1);
            h0 = split2(w.x, w.y, l0); h1 = split2(w.z, w.w, l1);
            *(uint2*)(sb + OFF_WH + off) = make_uint2(h0, h1);
            *(uint2*)(sb + OFF_WL + off) = make_uint2(l0, l1);
        }
    };

    float acc[4][4][4];
#pragma unroll
    for (int i = 0; i < 4; i++)
#pragma unroll
        for (int j = 0; j < 4; j++)
#pragma unroll
            for (int q = 0; q < 4; q++) acc[i][j][q] = 0.f;

    const uint32_t a_base = (uint32_t)((wm + (lane & 15)) * SROW + (lane >> 4) * 8) * 2;
    const uint32_t b_base = (uint32_t)((wn + (lane & 7) + ((lane >> 4) & 1) * 8) * SROW
                                       + ((lane >> 3) & 1) * 8) * 2;

    fill(0, 0);
    __syncthreads();

    for (int s = 0; s < 8; s++) {
        if (s < 7) fill((s + 1) & 1, (s + 1) * 64);   // overlap with compute

        const uint32_t stg = sbase + (s & 1) * STAGE_B;
#pragma unroll
        for (int kb16 = 0; kb16 < 4; kb16++) {
            const uint32_t koff = kb16 * 32;   // 16 halves = 32 bytes
            uint32_t bh[8], bl[8];
#pragma unroll
            for (int nh = 0; nh < 2; nh++) {
                uint32_t ba = stg + b_base + (uint32_t)(nh * 16 * SROW * 2) + koff;
                ldsm_x4(bh[nh*4+0], bh[nh*4+1], bh[nh*4+2], bh[nh*4+3], ba + OFF_WH);
                ldsm_x4(bl[nh*4+0], bl[nh*4+1], bl[nh*4+2], bl[nh*4+3], ba + OFF_WL);
            }
#pragma unroll
            for (int mi = 0; mi < 4; mi++) {
                uint32_t aa = stg + a_base + (uint32_t)(mi * 16 * SROW * 2) + koff;
                uint32_t ah[4], al[4];
                ldsm_x4(ah[0], ah[1], ah[2], ah[3], aa + OFF_AH);
                ldsm_x4(al[0], al[1], al[2], al[3], aa + OFF_AL);
#pragma unroll
                for (int ni = 0; ni < 4; ni++) {
                    mma_bf16(acc[mi][ni], ah, bh[ni*2], bh[ni*2+1]);
                    mma_bf16(acc[mi][ni], ah, bl[ni*2], bl[ni*2+1]);
                    mma_bf16(acc[mi][ni], al, bh[ni*2], bh[ni*2+1]);
                }
            }
        }
        __syncthreads();
    }

#pragma unroll
    for (int mi = 0; mi < 4; mi++) {
        int m = m0 + wm + mi * 16 + (lane >> 2);
#pragma unroll
        for (int ni = 0; ni < 4; ni++) {
            int nl = wn + ni * 8 + (lane & 3) * 2;
            float b0 = bias[nl], b1 = bias[nl + 1];
            float2 o0 = make_float2(acc[mi][ni][0] + b0, acc[mi][ni][1] + b1);
            float2 o1 = make_float2(acc[mi][ni][2] + b0, acc[mi][ni][3] + b1);
            if (relu) {
                o0.x = fmaxf(o0.x, 0.f); o0.y = fmaxf(o0.y, 0.f);
                o1.x = fmaxf(o1.x, 0.f); o1.y = fmaxf(o1.y, 0.f);
            }
            *(float2*)(C + (size_t)m * ldc + ccol0 + nl)       = o0;
            *(float2*)(C + (size_t)(m + 8) * ldc + ccol0 + nl) = o1;
        }
    }
}

// ---- fused QKV projection: grid (16, 12) ----------------------------------
__global__ __launch_bounds__(256) void mma_qkv_kernel(
    const float* __restrict__ X,
    const float* __restrict__ Wq, const float* __restrict__ bq,
    const float* __restrict__ Wk, const float* __restrict__ bk,
    const float* __restrict__ Wv, const float* __restrict__ bv)
{
    int m0   = blockIdx.x * 128;
    int ng   = blockIdx.y * 128;
    int sect = ng >> 9;
    int nl   = ng & 511;
    const float* W    = (sect == 0) ? Wq : (sect == 1) ? Wk : Wv;
    const float* bias = (sect == 0) ? bq : (sect == 1) ? bk : bv;
    tc_gemm_tile(X, W, bias + nl, g_QKV, 1536, m0, nl, ng, sect < 2);
}

// ---- output projection: grid (16, 4) --------------------------------------
__global__ __launch_bounds__(256) void mma_out_kernel(
    const float* __restrict__ Wo, const float* __restrict__ bo,
    float* __restrict__ out)
{
    int m0 = blockIdx.x * 128;
    int n0 = blockIdx.y * 128;
    tc_gemm_tile(g_attn, Wo, bo + n0, out, E_DIM, m0, n0, n0, false);
}

// ---------------------------------------------------------------------------
// Per-chunk sums: KV_c[dd][m] = sum_l k_exp[l][dd] * v[l][m];  z_c[dd]
// ---------------------------------------------------------------------------
__global__ __launch_bounds__(256) void chunksum_kernel()
{
    int c  = blockIdx.x;
    int n  = c >> 3, cc = c & 7;
    int b  = n >> 3, h  = n & 7;
    int tid = threadIdx.x;

    __shared__ float kb[8][64], vb[8][64], sl[8], clv[8];

    const int dd = tid >> 1;
    const int mg = (tid & 1) << 5;
    float acc[32];
#pragma unroll
    for (int m = 0; m < 32; m++) acc[m] = 0.f;
    float zacc = 0.f;

    const int ll  = tid >> 5;
    const int off = (tid & 31) << 2;

    for (int l0 = 0; l0 < CHUNK; l0 += 8) {
        __syncthreads();
        {
            int lg  = cc * CHUNK + l0 + ll;
            int r   = lg * 2 + b;
            int col = (off < 64) ? (512 + h * 64 + off) : (1024 + h * 64 + (off - 64));
            float4 val = *(const float4*)&g_QKV[(size_t)r * 1536 + col];
            if (off < 64) *(float4*)&kb[ll][off]      = val;
            else          *(float4*)&vb[ll][off - 64] = val;
            if (tid < 8) {
                float th = ANG * (float)(cc * CHUNK + l0 + tid + 1);
                sl[tid]  = sinf(th);
                clv[tid] = cosf(th);
            }
        }
        __syncthreads();
#pragma unroll
        for (int q = 0; q < 8; q++) {
            float ke = (dd < 64) ? (sl[q] * kb[q][dd]) : (clv[q] * kb[q][dd - 64]);
            zacc += ke;
#pragma unroll
            for (int m = 0; m < 32; m++)
                acc[m] = fmaf(ke, vb[q][mg + m], acc[m]);
        }
    }
    float* st = &g_state[(size_t)c * 8192 + (size_t)dd * 64 + mg];
#pragma unroll
    for (int m = 0; m < 32; m += 4)
        *(float4*)&st[m] = make_float4(acc[m], acc[m+1], acc[m+2], acc[m+3]);
    if (mg == 0) g_z[c * 128 + dd] = zacc;
}

// ---- exclusive prefix over chunks of each sequence: grid (16, 33) ---------
__global__ __launch_bounds__(256) void scan_kernel()
{
    int n = blockIdx.x;
    if (blockIdx.y < 32) {
        int e = blockIdx.y * 256 + threadIdx.x;
        float run = 0.f;
        for (int cc = 0; cc < 8; cc++) {
            size_t idx = (size_t)(n * 8 + cc) * 8192 + e;
            float t = g_state[idx];
            g_state[idx] = run;
            run += t;
        }
    } else if (threadIdx.x < 128) {
        int e = threadIdx.x;
        float run = 0.f;
        for (int cc = 0; cc < 8; cc++) {
            int idx = (n * 8 + cc) * 128 + e;
            float t = g_z[idx];
            g_z[idx] = run;
            run += t;
        }
    }
}

// ---------------------------------------------------------------------------
// Per-chunk attention, all-MMA.  grid: 128 blocks, 256 threads (8 warps).
// Smem: 6 bf16 arrays [128][72] (Qh,Ql,Kh/Sh,Kl/Sl,Vh,Vl) + fp32 tail.
// V col 64 = ones (gives rowsum(W)); S col 64 = z_prev (gives denom cross).
// ---------------------------------------------------------------------------
constexpr int CA_S    = 72;                 // halves per row
constexpr int CA_ARR  = 128 * CA_S * 2;     // 18432 B
constexpr int OQH = 0,           OQL = CA_ARR,
              OKH = 2 * CA_ARR,  OKL = 3 * CA_ARR,
              OVH = 4 * CA_ARR,  OVL = 5 * CA_ARR;
constexpr int CA_F32  = 6 * CA_ARR;         // 110592
constexpr int CA_SMEM = CA_F32 + 3 * 512 + 256;

__global__ __launch_bounds__(256) void chunkattn_kernel()
{
    extern __shared__ char casm[];
    const uint32_t sb = smem_u32(casm);
    float* ssin = (float*)(casm + CA_F32);
    float* scos = ssin + 128;
    float* sden = scos + 128;

    const int c  = blockIdx.x;
    const int n  = c >> 3, cc = c & 7;
    const int b  = n >> 3, h  = n & 7;
    const int tid = threadIdx.x, wid = tid >> 5, lane = tid & 31;

    // ---- load Q,K,V -> bf16 hi/lo smem ----
#pragma unroll
    for (int it = 0; it < 8; it++) {
        int idx = tid + it * 256;          // 0..2047 float4 slots
        int row = idx >> 4;                // l 0..127
        int col = (idx & 15) * 4;          // 0..60
        int rg  = (cc * CHUNK + row) * 2 + b;
        const float* src = &g_QKV[(size_t)rg * 1536 + h * 64 + col];
        float4 q4 = *(const float4*)(src);
        float4 k4 = *(const float4*)(src + 512);
        float4 v4 = *(const float4*)(src + 1024);
        uint32_t off = (uint32_t)(row * CA_S + col) * 2;
        uint32_t l0, l1, h0, h1;
        h0 = split2(q4.x, q4.y, l0); h1 = split2(q4.z, q4.w, l1);
        *(uint2*)(casm + OQH + off) = make_uint2(h0, h1);
        *(uint2*)(casm + OQL + off) = make_uint2(l0, l1);
        h0 = split2(k4.x, k4.y, l0); h1 = split2(k4.z, k4.w, l1);
        *(uint2*)(casm + OKH + off) = make_uint2(h0, h1);
        *(uint2*)(casm + OKL + off) = make_uint2(l0, l1);
        h0 = split2(v4.x, v4.y, l0); h1 = split2(v4.z, v4.w, l1);
        *(uint2*)(casm + OVH + off) = make_uint2(h0, h1);
        *(uint2*)(casm + OVL + off) = make_uint2(l0, l1);
    }
    if (tid < 128) {
        float th = ANG * (float)(cc * CHUNK + tid + 1);
        ssin[tid] = sinf(th);
        scos[tid] = cosf(th);
        uint32_t off = (uint32_t)(tid * CA_S + 64) * 2;
        *(uint4*)(casm + OVH + off) = make_uint4(0x00003f80u, 0u, 0u, 0u); // 1.0
        *(uint4*)(casm + OVL + off) = make_uint4(0u, 0u, 0u, 0u);
    }
    __syncthreads();

    // ---- Phase A: accW = Q K^T (split-bf16), 16 n-tiles per warp ----
    const int Rm = wid * 16;
    const uint32_t a_base = sb + (uint32_t)((Rm + (lane & 15)) * CA_S
                                            + ((lane >> 4) * 8)) * 2;
    const uint32_t bK_base = sb + (uint32_t)(((lane & 7) + ((lane >> 4) & 1) * 8) * CA_S
                                             + ((lane >> 3) & 1) * 8) * 2;

    float accW[16][4];
#pragma unroll
    for (int t = 0; t < 16; t++)
#pragma unroll
        for (int q = 0; q < 4; q++) accW[t][q] = 0.f;

#pragma unroll
    for (int kb = 0; kb < 4; kb++) {
        const uint32_t koff = kb * 32;
        uint32_t ah[4], al[4];
        ldsm_x4(ah[0], ah[1], ah[2], ah[3], a_base + OQH + koff);
        ldsm_x4(al[0], al[1], al[2], al[3], a_base + OQL + koff);
#pragma unroll
        for (int nh = 0; nh < 8; nh++) {
            uint32_t ba = bK_base + (uint32_t)(nh * 16 * CA_S * 2) + koff;
            uint32_t bh[4], bl[4];
            ldsm_x4(bh[0], bh[1], bh[2], bh[3], ba + OKH);
            ldsm_x4(bl[0], bl[1], bl[2], bl[3], ba + OKL);
            mma_bf16(accW[nh*2],   ah, bh[0], bh[1]);
            mma_bf16(accW[nh*2+1], ah, bh[2], bh[3]);
            mma_bf16(accW[nh*2],   ah, bl[0], bl[1]);
            mma_bf16(accW[nh*2+1], ah, bl[2], bl[3]);
            mma_bf16(accW[nh*2],   al, bh[0], bh[1]);
            mma_bf16(accW[nh*2+1], al, bh[2], bh[3]);
        }
    }
    __syncthreads();   // done reading sK; it becomes S below

    // ---- load S (prefix state) + z column into K region ----
#pragma unroll
    for (int it = 0; it < 8; it++) {
        int idx = tid + it * 256;
        int row = idx >> 4;
        int col = (idx & 15) * 4;
        float4 s4 = *(const float4*)&g_state[(size_t)c * 8192 + row * 64 + col];
        uint32_t off = (uint32_t)(row * CA_S + col) * 2;
        uint32_t l0, l1, h0, h1;
        h0 = split2(s4.x, s4.y, l0); h1 = split2(s4.z, s4.w, l1);
        *(uint2*)(casm + OKH + off) = make_uint2(h0, h1);
        *(uint2*)(casm + OKL + off) = make_uint2(l0, l1);
    }
    if (tid < 128) {
        float z = g_z[c * 128 + tid];
        uint32_t zl, zh = split2(z, 0.f, zl);
        uint32_t off = (uint32_t)(tid * CA_S + 64) * 2;
        *(uint4*)(casm + OKH + off) = make_uint4(zh, 0u, 0u, 0u);
        *(uint4*)(casm + OKL + off) = make_uint4(zl, 0u, 0u, 0u);
    }

    // ---- apply cos-difference factor + causal mask in registers ----
    const int r0 = Rm + (lane >> 2), r1 = r0 + 8;
    const float sl0 = ssin[r0], cl0 = scos[r0];
    const float sl1 = ssin[r1], cl1 = scos[r1];
#pragma unroll
    for (int t = 0; t < 16; t++) {
        int c0 = t * 8 + (lane & 3) * 2, c1 = c0 + 1;
        float sj0 = ssin[c0], cj0 = scos[c0];
        float sj1 = ssin[c1], cj1 = scos[c1];
        accW[t][0] = (c0 <= r0) ? accW[t][0] * (sl0*sj0 + cl0*cj0) : 0.f;
        accW[t][1] = (c1 <= r0) ? accW[t][1] * (sl0*sj1 + cl0*cj1) : 0.f;
        accW[t][2] = (c0 <= r1) ? accW[t][2] * (sl1*sj0 + cl1*cj0) : 0.f;
        accW[t][3] = (c1 <= r1) ? accW[t][3] * (sl1*sj1 + cl1*cj1) : 0.f;
    }
    __syncthreads();   // S ready

    // ---- Phase B1: wv = W * Vext  (Vext col 64 = ones -> rowsum) ----
    float wv[9][4];
#pragma unroll
    for (int t = 0; t < 9; t++)
#pragma unroll
        for (int q = 0; q < 4; q++) wv[t][q] = 0.f;

#pragma unroll
    for (int kj = 0; kj < 8; kj++) {
        uint32_t ah[4], al[4];
        ah[0] = split2(accW[2*kj][0],   accW[2*kj][1],   al[0]);
        ah[1] = split2(accW[2*kj][2],   accW[2*kj][3],   al[1]);
        ah[2] = split2(accW[2*kj+1][0], accW[2*kj+1][1], al[2]);
        ah[3] = split2(accW[2*kj+1][2], accW[2*kj+1][3], al[3]);
        uint32_t tb = sb + (uint32_t)((kj * 16 + (lane & 15)) * CA_S
                                      + ((lane >> 4) * 8)) * 2;
#pragma unroll
        for (int ng = 0; ng < 5; ng++) {
            uint32_t tba = tb + ng * 32;
            uint32_t bh[4], bl[4];
            ldsm_x4_t(bh[0], bh[1], bh[2], bh[3], tba + OVH);
            ldsm_x4_t(bl[0], bl[1], bl[2], bl[3], tba + OVL);
            mma_bf16(wv[2*ng], ah, bh[0], bh[1]);
            mma_bf16(wv[2*ng], ah, bl[0], bl[1]);
            mma_bf16(wv[2*ng], al, bh[0], bh[1]);
            if (ng < 4) {
                mma_bf16(wv[2*ng+1], ah, bh[2], bh[3]);
                mma_bf16(wv[2*ng+1], ah, bl[2], bl[3]);
                mma_bf16(wv[2*ng+1], al, bh[2], bh[3]);
            }
        }
    }

    // ---- Phase B2: Y1 = q*S[0:64], Y2 = q*S[64:128]  (col 64 = z) ----
    float Y1[9][4], Y2[9][4];
#pragma unroll
    for (int t = 0; t < 9; t++)
#pragma unroll
        for (int q = 0; q < 4; q++) { Y1[t][q] = 0.f; Y2[t][q] = 0.f; }

#pragma unroll
    for (int half = 0; half < 2; half++) {
        float (*Y)[4] = half ? Y2 : Y1;
#pragma unroll
        for (int kq = 0; kq < 4; kq++) {
            uint32_t qh[4], ql[4];
            ldsm_x4(qh[0], qh[1], qh[2], qh[3], a_base + OQH + kq * 32);
            ldsm_x4(ql[0], ql[1], ql[2], ql[3], a_base + OQL + kq * 32);
            uint32_t tb = sb + (uint32_t)((half * 64 + kq * 16 + (lane & 15)) * CA_S
                                          + ((lane >> 4) * 8)) * 2;
#pragma unroll
            for (int ng = 0; ng < 5; ng++) {
                uint32_t tba = tb + ng * 32;
                uint32_t sh[4], sl4[4];
                ldsm_x4_t(sh[0], sh[1], sh[2], sh[3], tba + OKH);
                ldsm_x4_t(sl4[0], sl4[1], sl4[2], sl4[3], tba + OKL);
                mma_bf16(Y[2*ng], qh, sh[0], sh[1]);
                mma_bf16(Y[2*ng], qh, sl4[0], sl4[1]);
                mma_bf16(Y[2*ng], ql, sh[0], sh[1]);
                if (ng < 4) {
                    mma_bf16(Y[2*ng+1], qh, sh[2], sh[3]);
                    mma_bf16(Y[2*ng+1], qh, sl4[2], sl4[3]);
                    mma_bf16(Y[2*ng+1], ql, sh[2], sh[3]);
                }
            }
        }
    }

    // ---- denominators (col 64 = tile 8, lanes with lane&3==0) ----
    if ((lane & 3) == 0) {
        float d0 = wv[8][0] + sl0 * Y1[8][0] + cl0 * Y2[8][0];
        float d1 = wv[8][2] + sl1 * Y1[8][2] + cl1 * Y2[8][2];
        sden[r0] = fmaxf(d0, EPSV);
        sden[r1] = fmaxf(d1, EPSV);
    }
    __syncthreads();
    const float inv0 = 1.0f / sden[r0];
    const float inv1 = 1.0f / sden[r1];

    // ---- combine + write attn ----
    const int rg0 = (cc * CHUNK + r0) * 2 + b;
    float* dst0 = &g_attn[(size_t)rg0 * E_DIM + h * 64];
    float* dst1 = dst0 + 16 * E_DIM;   // row r1 = r0+8 -> +16 flat rows
#pragma unroll
    for (int t = 0; t < 8; t++) {
        int c0 = t * 8 + (lane & 3) * 2;
        float2 o0, o1;
        o0.x = (wv[t][0] + sl0 * Y1[t][0] + cl0 * Y2[t][0]) * inv0;
        o0.y = (wv[t][1] + sl0 * Y1[t][1] + cl0 * Y2[t][1]) * inv0;
        o1.x = (wv[t][2] + sl1 * Y1[t][2] + cl1 * Y2[t][2]) * inv1;
        o1.y = (wv[t][3] + sl1 * Y1[t][3] + cl1 * Y2[t][3]) * inv1;
        *(float2*)(dst0 + c0) = o0;
        *(float2*)(dst1 + c0) = o1;
    }
}

// ---------------------------------------------------------------------------
extern "C" void kernel_launch(void* const* d_in, const int* in_sizes, int n_in,
                              void* d_out, int out_size)
{
    const float* query = (const float*)d_in[0];
    const float* Wq = (const float*)d_in[1];
    const float* bq = (const float*)d_in[2];
    const float* Wk = (const float*)d_in[3];
    const float* bk = (const float*)d_in[4];
    const float* Wv = (const float*)d_in[5];
    const float* bv = (const float*)d_in[6];
    const float* Wo = (const float*)d_in[7];
    const float* bo = (const float*)d_in[8];
    float* out = (float*)d_out;

    cudaFuncSetAttribute(chunkattn_kernel,
                         cudaFuncAttributeMaxDynamicSharedMemorySize, CA_SMEM);
    cudaFuncSetAttribute(mma_qkv_kernel,
                         cudaFuncAttributeMaxDynamicSharedMemorySize, TC_SMEM);
    cudaFuncSetAttribute(mma_out_kernel,
                         cudaFuncAttributeMaxDynamicSharedMemorySize, TC_SMEM);

    mma_qkv_kernel<<<dim3(16, 12), 256, TC_SMEM>>>(query, Wq, bq, Wk, bk, Wv, bv);
    chunksum_kernel<<<128, 256>>>();
    scan_kernel<<<dim3(16, 33), 256>>>();
    chunkattn_kernel<<<128, 256, CA_SMEM>>>();
    mma_out_kernel<<<dim3(16, 4), 256, TC_SMEM>>>(Wo, bo, out);
}

// round 6
// speedup vs baseline: 1.5962x; 1.5962x over previous
#include <cuda_runtime.h>
#include <cuda_bf16.h>
#include <math.h>
#include <stdint.h>

// ---------------------------------------------------------------------------
// CosformerAttention: bsz=2, L=1024, E=512, H=8, D=64
// Flat row-major view: X[2048][512], row r = l*2 + b  (pure reshape in ref).
//   0) convert : X, Wq..Wo fp32 -> bf16 hi/lo global arrays (split-bf16 prep)
//   1) mma_qkv : Q=relu(X Wq^T+bq), K=relu(X Wk^T+bk), V=X Wv^T+bv  [HMMA]
//      mainloop = cp.async + ldmatrix + mma only (conversion pre-hoisted)
//   2) chunksum: per 128-chunk  KV_c[128][64] = sum k_exp (x) v ; z_c
//   3) scan    : exclusive prefix over the 8 chunks of each sequence
//   4) chunkattn: all-MMA; writes attn directly as bf16 hi/lo
//   5) mma_out : out = attn Wo^T + bo                               [HMMA]
// All tensor math: split-bf16 (hi+lo, 3 products) m16n8k16, fp32 accumulate.
// ---------------------------------------------------------------------------

constexpr int E_DIM  = 512;
constexpr int NROWS  = 2048;   // L * bsz
constexpr int CHUNK  = 128;
constexpr int NCHUNK = 128;    // 16 sequences * 8 chunks
constexpr float ANG  = 1.5707963267948966f / 1024.0f;  // (pi/2)/L
constexpr float EPSV = 1e-6f;

// scratch (device globals: allocation-free rule)
__device__ __align__(16) float    g_QKV[NROWS * 1536];        // Q|K|V fp32
__device__ __align__(16) float    g_state[NCHUNK * 128 * 64]; // chunk KV state
__device__ __align__(16) float    g_z[NCHUNK * 128];          // chunk k-sum
__device__ __align__(16) uint16_t g_Xh[NROWS * E_DIM];        // X bf16 hi
__device__ __align__(16) uint16_t g_Xl[NROWS * E_DIM];        // X bf16 lo
__device__ __align__(16) uint16_t g_Wh[4 * E_DIM * E_DIM];    // Wq|Wk|Wv|Wo hi
__device__ __align__(16) uint16_t g_Wl[4 * E_DIM * E_DIM];    // Wq|Wk|Wv|Wo lo
__device__ __align__(16) uint16_t g_Ah[NROWS * E_DIM];        // attn bf16 hi
__device__ __align__(16) uint16_t g_Al[NROWS * E_DIM];        // attn bf16 lo

// ---------------------------------------------------------------------------
// helpers
// ---------------------------------------------------------------------------
__device__ __forceinline__ uint32_t smem_u32(const void* p) {
    uint32_t a;
    asm("{ .reg .u64 t; cvta.to.shared.u64 t, %1; cvt.u32.u64 %0, t; }"
        : "=r"(a) : "l"(p));
    return a;
}
__device__ __forceinline__ void ldsm_x4(uint32_t& r0, uint32_t& r1,
                                        uint32_t& r2, uint32_t& r3, uint32_t a) {
    asm volatile("ldmatrix.sync.aligned.m8n8.x4.shared.b16 {%0,%1,%2,%3}, [%4];"
                 : "=r"(r0), "=r"(r1), "=r"(r2), "=r"(r3) : "r"(a));
}
__device__ __forceinline__ void ldsm_x4_t(uint32_t& r0, uint32_t& r1,
                                          uint32_t& r2, uint32_t& r3, uint32_t a) {
    asm volatile("ldmatrix.sync.aligned.m8n8.x4.trans.shared.b16 {%0,%1,%2,%3}, [%4];"
                 : "=r"(r0), "=r"(r1), "=r"(r2), "=r"(r3) : "r"(a));
}
__device__ __forceinline__ void mma_bf16(float* c, const uint32_t* a,
                                         uint32_t b0, uint32_t b1) {
    asm volatile(
        "mma.sync.aligned.m16n8k16.row.col.f32.bf16.bf16.f32 "
        "{%0,%1,%2,%3}, {%4,%5,%6,%7}, {%8,%9}, {%0,%1,%2,%3};"
        : "+f"(c[0]), "+f"(c[1]), "+f"(c[2]), "+f"(c[3])
        : "r"(a[0]), "r"(a[1]), "r"(a[2]), "r"(a[3]), "r"(b0), "r"(b1));
}
// split (x0,x1) into packed bf16 hi pair (returned) and lo pair (out)
__device__ __forceinline__ uint32_t split2(float x0, float x1, uint32_t& lo) {
    uint32_t hi;
    asm("cvt.rn.bf16x2.f32 %0, %1, %2;" : "=r"(hi) : "f"(x1), "f"(x0));
    float h0 = __uint_as_float(hi << 16);
    float h1 = __uint_as_float(hi & 0xFFFF0000u);
    asm("cvt.rn.bf16x2.f32 %0, %1, %2;" : "=r"(lo) : "f"(x1 - h1), "f"(x0 - h0));
    return hi;
}
__device__ __forceinline__ void cp16(uint32_t dst, const void* src) {
    asm volatile("cp.async.cg.shared.global [%0], [%1], 16;"
                 :: "r"(dst), "l"(src) : "memory");
}
#define CP_COMMIT() asm volatile("cp.async.commit_group;" ::: "memory")
#define CP_WAIT(N)  asm volatile("cp.async.wait_group %0;" :: "n"(N) : "memory")

// ---------------------------------------------------------------------------
// convert: fp32 -> bf16 hi/lo split for X and the four weight matrices
// grid (1024, 5): y=0 -> X, y=1..4 -> Wq,Wk,Wv,Wo
// ---------------------------------------------------------------------------
__global__ __launch_bounds__(256) void convert_kernel(
    const float* __restrict__ X,
    const float* __restrict__ Wq, const float* __restrict__ Wk,
    const float* __restrict__ Wv, const float* __restrict__ Wo)
{
    int y = blockIdx.y;
    const float* src;
    uint16_t *dh, *dl;
    int n4;
    if (y == 0) { src = X; dh = g_Xh; dl = g_Xl; n4 = NROWS * E_DIM / 4; }
    else {
        src = (y == 1) ? Wq : (y == 2) ? Wk : (y == 3) ? Wv : Wo;
        dh = g_Wh + (y - 1) * E_DIM * E_DIM;
        dl = g_Wl + (y - 1) * E_DIM * E_DIM;
        n4 = E_DIM * E_DIM / 4;
    }
    int idx = blockIdx.x * 256 + threadIdx.x;
    if (idx < n4) {
        float4 v = ((const float4*)src)[idx];
        uint32_t l0, l1;
        uint32_t h0 = split2(v.x, v.y, l0), h1 = split2(v.z, v.w, l1);
        ((uint2*)dh)[idx] = make_uint2(h0, h1);
        ((uint2*)dl)[idx] = make_uint2(l0, l1);
    }
}

// ---------------------------------------------------------------------------
// HMMA split-bf16 GEMM tile (cp.async mainloop):
//   C[128x128] = A[128x512] * B[row0..+128][512]^T + bias
// smem: 2 stages x 4 arrays (AH, AL, BH, BL), 128 rows x 64 halves, stride 72
// ---------------------------------------------------------------------------
constexpr int SROW    = 72;                 // halves per smem row (144 B)
constexpr int ARR_B   = 128 * SROW * 2;     // 18432
constexpr int OFF_AH  = 0;
constexpr int OFF_AL  = ARR_B;
constexpr int OFF_BH  = 2 * ARR_B;
constexpr int OFF_BL  = 3 * ARR_B;
constexpr int STAGE_B = 4 * ARR_B;          // 73728
constexpr int TC_SMEM = 2 * STAGE_B;        // 147456

__device__ void tc_gemm_tile(
    const uint16_t* __restrict__ Ah, const uint16_t* __restrict__ Al,
    const uint16_t* __restrict__ Bh, const uint16_t* __restrict__ Bl,
    const float* __restrict__ bias, float* __restrict__ C,
    int ldc, int m0, int ccol0, bool relu)
{
    extern __shared__ char dynsm[];
    const uint32_t sbase = smem_u32(dynsm);
    const int tid  = threadIdx.x;
    const int wid  = tid >> 5, lane = tid & 31;
    const int wm   = (wid & 1) * 64;
    const int wn   = (wid >> 1) * 32;

    const uint16_t* Ahb = Ah + (size_t)m0 * E_DIM;
    const uint16_t* Alb = Al + (size_t)m0 * E_DIM;

    auto fill = [&](int st, int k0) {
        uint32_t sb = sbase + st * STAGE_B;
#pragma unroll
        for (int i = 0; i < 4; i++) {
            int idx = tid + i * 256;            // 0..1023
            int row = idx >> 3, cc = idx & 7;   // 8 x 16B chunks per row
            uint32_t d = sb + (uint32_t)(row * 144 + cc * 16);
            size_t  go = (size_t)row * E_DIM + k0 + cc * 8;
            cp16(d + OFF_AH, Ahb + go);
            cp16(d + OFF_AL, Alb + go);
            cp16(d + OFF_BH, Bh + go);
            cp16(d + OFF_BL, Bl + go);
        }
        CP_COMMIT();
    };

    float acc[4][4][4];
#pragma unroll
    for (int i = 0; i < 4; i++)
#pragma unroll
        for (int j = 0; j < 4; j++)
#pragma unroll
            for (int q = 0; q < 4; q++) acc[i][j][q] = 0.f;

    const uint32_t a_base = (uint32_t)((wm + (lane & 15)) * SROW + (lane >> 4) * 8) * 2;
    const uint32_t b_base = (uint32_t)((wn + (lane & 7) + ((lane >> 4) & 1) * 8) * SROW
                                       + ((lane >> 3) & 1) * 8) * 2;

    fill(0, 0);
    fill(1, 64);

    for (int s = 0; s < 8; s++) {
        if (s == 7) { CP_WAIT(0); } else { CP_WAIT(1); }
        __syncthreads();

        const uint32_t stg = sbase + (s & 1) * STAGE_B;
#pragma unroll
        for (int kb16 = 0; kb16 < 4; kb16++) {
            const uint32_t koff = kb16 * 32;
            uint32_t bh[8], bl[8];
#pragma unroll
            for (int nh = 0; nh < 2; nh++) {
                uint32_t ba = stg + b_base + (uint32_t)(nh * 16 * SROW * 2) + koff;
                ldsm_x4(bh[nh*4+0], bh[nh*4+1], bh[nh*4+2], bh[nh*4+3], ba + OFF_BH);
                ldsm_x4(bl[nh*4+0], bl[nh*4+1], bl[nh*4+2], bl[nh*4+3], ba + OFF_BL);
            }
#pragma unroll
            for (int mi = 0; mi < 4; mi++) {
                uint32_t aa = stg + a_base + (uint32_t)(mi * 16 * SROW * 2) + koff;
                uint32_t ah[4], al[4];
                ldsm_x4(ah[0], ah[1], ah[2], ah[3], aa + OFF_AH);
                ldsm_x4(al[0], al[1], al[2], al[3], aa + OFF_AL);
#pragma unroll
                for (int ni = 0; ni < 4; ni++) {
                    mma_bf16(acc[mi][ni], ah, bh[ni*2], bh[ni*2+1]);
                    mma_bf16(acc[mi][ni], ah, bl[ni*2], bl[ni*2+1]);
                    mma_bf16(acc[mi][ni], al, bh[ni*2], bh[ni*2+1]);
                }
            }
        }
        __syncthreads();
        if (s + 2 < 8) fill(s & 1, (s + 2) * 64);
    }

#pragma unroll
    for (int mi = 0; mi < 4; mi++) {
        int m = m0 + wm + mi * 16 + (lane >> 2);
#pragma unroll
        for (int ni = 0; ni < 4; ni++) {
            int nl = wn + ni * 8 + (lane & 3) * 2;
            float b0 = bias[nl], b1 = bias[nl + 1];
            float2 o0 = make_float2(acc[mi][ni][0] + b0, acc[mi][ni][1] + b1);
            float2 o1 = make_float2(acc[mi][ni][2] + b0, acc[mi][ni][3] + b1);
            if (relu) {
                o0.x = fmaxf(o0.x, 0.f); o0.y = fmaxf(o0.y, 0.f);
                o1.x = fmaxf(o1.x, 0.f); o1.y = fmaxf(o1.y, 0.f);
            }
            *(float2*)(C + (size_t)m * ldc + ccol0 + nl)       = o0;
            *(float2*)(C + (size_t)(m + 8) * ldc + ccol0 + nl) = o1;
        }
    }
}

// ---- fused QKV projection: grid (16, 12) ----------------------------------
__global__ __launch_bounds__(256) void mma_qkv_kernel(
    const float* __restrict__ bq, const float* __restrict__ bk,
    const float* __restrict__ bv)
{
    int m0   = blockIdx.x * 128;
    int ng   = blockIdx.y * 128;
    int sect = ng >> 9;
    int nl   = ng & 511;
    const float* bias = (sect == 0) ? bq : (sect == 1) ? bk : bv;
    const uint16_t* Bh = g_Wh + (size_t)sect * E_DIM * E_DIM + (size_t)nl * E_DIM;
    const uint16_t* Bl = g_Wl + (size_t)sect * E_DIM * E_DIM + (size_t)nl * E_DIM;
    tc_gemm_tile(g_Xh, g_Xl, Bh, Bl, bias + nl, g_QKV, 1536, m0, ng, sect < 2);
}

// ---- output projection: grid (16, 4) --------------------------------------
__global__ __launch_bounds__(256) void mma_out_kernel(
    const float* __restrict__ bo, float* __restrict__ out)
{
    int m0 = blockIdx.x * 128;
    int n0 = blockIdx.y * 128;
    const uint16_t* Bh = g_Wh + (size_t)3 * E_DIM * E_DIM + (size_t)n0 * E_DIM;
    const uint16_t* Bl = g_Wl + (size_t)3 * E_DIM * E_DIM + (size_t)n0 * E_DIM;
    tc_gemm_tile(g_Ah, g_Al, Bh, Bl, bo + n0, out, E_DIM, m0, n0, false);
}

// ---------------------------------------------------------------------------
// Per-chunk sums: KV_c[dd][m] = sum_l k_exp[l][dd] * v[l][m];  z_c[dd]
// ---------------------------------------------------------------------------
__global__ __launch_bounds__(256) void chunksum_kernel()
{
    int c  = blockIdx.x;
    int n  = c >> 3, cc = c & 7;
    int b  = n >> 3, h  = n & 7;
    int tid = threadIdx.x;

    __shared__ float kb[8][64], vb[8][64], sl[8], clv[8];

    const int dd = tid >> 1;
    const int mg = (tid & 1) << 5;
    float acc[32];
#pragma unroll
    for (int m = 0; m < 32; m++) acc[m] = 0.f;
    float zacc = 0.f;

    const int ll  = tid >> 5;
    const int off = (tid & 31) << 2;

    for (int l0 = 0; l0 < CHUNK; l0 += 8) {
        __syncthreads();
        {
            int lg  = cc * CHUNK + l0 + ll;
            int r   = lg * 2 + b;
            int col = (off < 64) ? (512 + h * 64 + off) : (1024 + h * 64 + (off - 64));
            float4 val = *(const float4*)&g_QKV[(size_t)r * 1536 + col];
            if (off < 64) *(float4*)&kb[ll][off]      = val;
            else          *(float4*)&vb[ll][off - 64] = val;
            if (tid < 8) {
                float th = ANG * (float)(cc * CHUNK + l0 + tid + 1);
                sl[tid]  = sinf(th);
                clv[tid] = cosf(th);
            }
        }
        __syncthreads();
#pragma unroll
        for (int q = 0; q < 8; q++) {
            float ke = (dd < 64) ? (sl[q] * kb[q][dd]) : (clv[q] * kb[q][dd - 64]);
            zacc += ke;
#pragma unroll
            for (int m = 0; m < 32; m++)
                acc[m] = fmaf(ke, vb[q][mg + m], acc[m]);
        }
    }
    float* st = &g_state[(size_t)c * 8192 + (size_t)dd * 64 + mg];
#pragma unroll
    for (int m = 0; m < 32; m += 4)
        *(float4*)&st[m] = make_float4(acc[m], acc[m+1], acc[m+2], acc[m+3]);
    if (mg == 0) g_z[c * 128 + dd] = zacc;
}

// ---- exclusive prefix over chunks of each sequence: grid (16, 33) ---------
__global__ __launch_bounds__(256) void scan_kernel()
{
    int n = blockIdx.x;
    if (blockIdx.y < 32) {
        int e = blockIdx.y * 256 + threadIdx.x;
        float run = 0.f;
        for (int cc = 0; cc < 8; cc++) {
            size_t idx = (size_t)(n * 8 + cc) * 8192 + e;
            float t = g_state[idx];
            g_state[idx] = run;
            run += t;
        }
    } else if (threadIdx.x < 128) {
        int e = threadIdx.x;
        float run = 0.f;
        for (int cc = 0; cc < 8; cc++) {
            int idx = (n * 8 + cc) * 128 + e;
            float t = g_z[idx];
            g_z[idx] = run;
            run += t;
        }
    }
}

// ---------------------------------------------------------------------------
// Per-chunk attention, all-MMA.  grid: 128 blocks, 256 threads (8 warps).
// Smem: 6 bf16 arrays [128][72] (Qh,Ql,Kh/Sh,Kl/Sl,Vh,Vl) + fp32 tail.
// V col 64 = ones (gives rowsum(W)); S col 64 = z_prev (gives denom cross).
// Output written as bf16 hi/lo (feeds mma_out directly).
// ---------------------------------------------------------------------------
constexpr int CA_S    = 72;                 // halves per row
constexpr int CA_ARR  = 128 * CA_S * 2;     // 18432 B
constexpr int OQH = 0,           OQL = CA_ARR,
              OKH = 2 * CA_ARR,  OKL = 3 * CA_ARR,
              OVH = 4 * CA_ARR,  OVL = 5 * CA_ARR;
constexpr int CA_F32  = 6 * CA_ARR;
constexpr int CA_SMEM = CA_F32 + 3 * 512 + 256;

__global__ __launch_bounds__(256) void chunkattn_kernel()
{
    extern __shared__ char casm[];
    const uint32_t sb = smem_u32(casm);
    float* ssin = (float*)(casm + CA_F32);
    float* scos = ssin + 128;
    float* sden = scos + 128;

    const int c  = blockIdx.x;
    const int n  = c >> 3, cc = c & 7;
    const int b  = n >> 3, h  = n & 7;
    const int tid = threadIdx.x, wid = tid >> 5, lane = tid & 31;

    // ---- load Q,K,V -> bf16 hi/lo smem ----
#pragma unroll
    for (int it = 0; it < 8; it++) {
        int idx = tid + it * 256;
        int row = idx >> 4;
        int col = (idx & 15) * 4;
        int rg  = (cc * CHUNK + row) * 2 + b;
        const float* src = &g_QKV[(size_t)rg * 1536 + h * 64 + col];
        float4 q4 = *(const float4*)(src);
        float4 k4 = *(const float4*)(src + 512);
        float4 v4 = *(const float4*)(src + 1024);
        uint32_t off = (uint32_t)(row * CA_S + col) * 2;
        uint32_t l0, l1, h0, h1;
        h0 = split2(q4.x, q4.y, l0); h1 = split2(q4.z, q4.w, l1);
        *(uint2*)(casm + OQH + off) = make_uint2(h0, h1);
        *(uint2*)(casm + OQL + off) = make_uint2(l0, l1);
        h0 = split2(k4.x, k4.y, l0); h1 = split2(k4.z, k4.w, l1);
        *(uint2*)(casm + OKH + off) = make_uint2(h0, h1);
        *(uint2*)(casm + OKL + off) = make_uint2(l0, l1);
        h0 = split2(v4.x, v4.y, l0); h1 = split2(v4.z, v4.w, l1);
        *(uint2*)(casm + OVH + off) = make_uint2(h0, h1);
        *(uint2*)(casm + OVL + off) = make_uint2(l0, l1);
    }
    if (tid < 128) {
        float th = ANG * (float)(cc * CHUNK + tid + 1);
        ssin[tid] = sinf(th);
        scos[tid] = cosf(th);
        uint32_t off = (uint32_t)(tid * CA_S + 64) * 2;
        *(uint4*)(casm + OVH + off) = make_uint4(0x00003f80u, 0u, 0u, 0u); // 1.0
        *(uint4*)(casm + OVL + off) = make_uint4(0u, 0u, 0u, 0u);
    }
    __syncthreads();

    // ---- Phase A: accW = Q K^T (split-bf16), 16 n-tiles per warp ----
    const int Rm = wid * 16;
    const uint32_t a_base = sb + (uint32_t)((Rm + (lane & 15)) * CA_S
                                            + ((lane >> 4) * 8)) * 2;
    const uint32_t bK_base = sb + (uint32_t)(((lane & 7) + ((lane >> 4) & 1) * 8) * CA_S
                                             + ((lane >> 3) & 1) * 8) * 2;

    float accW[16][4];
#pragma unroll
    for (int t = 0; t < 16; t++)
#pragma unroll
        for (int q = 0; q < 4; q++) accW[t][q] = 0.f;

#pragma unroll
    for (int kb = 0; kb < 4; kb++) {
        const uint32_t koff = kb * 32;
        uint32_t ah[4], al[4];
        ldsm_x4(ah[0], ah[1], ah[2], ah[3], a_base + OQH + koff);
        ldsm_x4(al[0], al[1], al[2], al[3], a_base + OQL + koff);
#pragma unroll
        for (int nh = 0; nh < 8; nh++) {
            uint32_t ba = bK_base + (uint32_t)(nh * 16 * CA_S * 2) + koff;
            uint32_t bh[4], bl[4];
            ldsm_x4(bh[0], bh[1], bh[2], bh[3], ba + OKH);
            ldsm_x4(bl[0], bl[1], bl[2], bl[3], ba + OKL);
            mma_bf16(accW[nh*2],   ah, bh[0], bh[1]);
            mma_bf16(accW[nh*2+1], ah, bh[2], bh[3]);
            mma_bf16(accW[nh*2],   ah, bl[0], bl[1]);
            mma_bf16(accW[nh*2+1], ah, bl[2], bl[3]);
            mma_bf16(accW[nh*2],   al, bh[0], bh[1]);
            mma_bf16(accW[nh*2+1], al, bh[2], bh[3]);
        }
    }
    __syncthreads();   // done reading sK; region becomes S below

    // ---- load S (prefix state) + z column into K region ----
#pragma unroll
    for (int it = 0; it < 8; it++) {
        int idx = tid + it * 256;
        int row = idx >> 4;
        int col = (idx & 15) * 4;
        float4 s4 = *(const float4*)&g_state[(size_t)c * 8192 + row * 64 + col];
        uint32_t off = (uint32_t)(row * CA_S + col) * 2;
        uint32_t l0, l1, h0, h1;
        h0 = split2(s4.x, s4.y, l0); h1 = split2(s4.z, s4.w, l1);
        *(uint2*)(casm + OKH + off) = make_uint2(h0, h1);
        *(uint2*)(casm + OKL + off) = make_uint2(l0, l1);
    }
    if (tid < 128) {
        float z = g_z[c * 128 + tid];
        uint32_t zl, zh = split2(z, 0.f, zl);
        uint32_t off = (uint32_t)(tid * CA_S + 64) * 2;
        *(uint4*)(casm + OKH + off) = make_uint4(zh, 0u, 0u, 0u);
        *(uint4*)(casm + OKL + off) = make_uint4(zl, 0u, 0u, 0u);
    }

    // ---- apply cos-difference factor + causal mask in registers ----
    const int r0 = Rm + (lane >> 2), r1 = r0 + 8;
    const float sl0 = ssin[r0], cl0 = scos[r0];
    const float sl1 = ssin[r1], cl1 = scos[r1];
#pragma unroll
    for (int t = 0; t < 16; t++) {
        int c0 = t * 8 + (lane & 3) * 2, c1 = c0 + 1;
        float sj0 = ssin[c0], cj0 = scos[c0];
        float sj1 = ssin[c1], cj1 = scos[c1];
        accW[t][0] = (c0 <= r0) ? accW[t][0] * (sl0*sj0 + cl0*cj0) : 0.f;
        accW[t][1] = (c1 <= r0) ? accW[t][1] * (sl0*sj1 + cl0*cj1) : 0.f;
        accW[t][2] = (c0 <= r1) ? accW[t][2] * (sl1*sj0 + cl1*cj0) : 0.f;
        accW[t][3] = (c1 <= r1) ? accW[t][3] * (sl1*sj1 + cl1*cj1) : 0.f;
    }
    __syncthreads();   // S ready

    // ---- Phase B1: wv = W * Vext  (Vext col 64 = ones -> rowsum) ----
    float wv[9][4];
#pragma unroll
    for (int t = 0; t < 9; t++)
#pragma unroll
        for (int q = 0; q < 4; q++) wv[t][q] = 0.f;

#pragma unroll
    for (int kj = 0; kj < 8; kj++) {
        uint32_t ah[4], al[4];
        ah[0] = split2(accW[2*kj][0],   accW[2*kj][1],   al[0]);
        ah[1] = split2(accW[2*kj][2],   accW[2*kj][3],   al[1]);
        ah[2] = split2(accW[2*kj+1][0], accW[2*kj+1][1], al[2]);
        ah[3] = split2(accW[2*kj+1][2], accW[2*kj+1][3], al[3]);
        uint32_t tb = sb + (uint32_t)((kj * 16 + (lane & 15)) * CA_S
                                      + ((lane >> 4) * 8)) * 2;
#pragma unroll
        for (int ng = 0; ng < 5; ng++) {
            uint32_t tba = tb + ng * 32;
            uint32_t bh[4], bl[4];
            ldsm_x4_t(bh[0], bh[1], bh[2], bh[3], tba + OVH);
            ldsm_x4_t(bl[0], bl[1], bl[2], bl[3], tba + OVL);
            mma_bf16(wv[2*ng], ah, bh[0], bh[1]);
            mma_bf16(wv[2*ng], ah, bl[0], bl[1]);
            mma_bf16(wv[2*ng], al, bh[0], bh[1]);
            if (ng < 4) {
                mma_bf16(wv[2*ng+1], ah, bh[2], bh[3]);
                mma_bf16(wv[2*ng+1], ah, bl[2], bl[3]);
                mma_bf16(wv[2*ng+1], al, bh[2], bh[3]);
            }
        }
    }

    // ---- Phase B2: Y1 = q*S[0:64], Y2 = q*S[64:128]  (col 64 = z) ----
    float Y1[9][4], Y2[9][4];
#pragma unroll
    for (int t = 0; t < 9; t++)
#pragma unroll
        for (int q = 0; q < 4; q++) { Y1[t][q] = 0.f; Y2[t][q] = 0.f; }

#pragma unroll
    for (int half = 0; half < 2; half++) {
        float (*Y)[4] = half ? Y2 : Y1;
#pragma unroll
        for (int kq = 0; kq < 4; kq++) {
            uint32_t qh[4], ql[4];
            ldsm_x4(qh[0], qh[1], qh[2], qh[3], a_base + OQH + kq * 32);
            ldsm_x4(ql[0], ql[1], ql[2], ql[3], a_base + OQL + kq * 32);
            uint32_t tb = sb + (uint32_t)((half * 64 + kq * 16 + (lane & 15)) * CA_S
                                          + ((lane >> 4) * 8)) * 2;
#pragma unroll
            for (int ng = 0; ng < 5; ng++) {
                uint32_t tba = tb + ng * 32;
                uint32_t sh[4], sl4[4];
                ldsm_x4_t(sh[0], sh[1], sh[2], sh[3], tba + OKH);
                ldsm_x4_t(sl4[0], sl4[1], sl4[2], sl4[3], tba + OKL);
                mma_bf16(Y[2*ng], qh, sh[0], sh[1]);
                mma_bf16(Y[2*ng], qh, sl4[0], sl4[1]);
                mma_bf16(Y[2*ng], ql, sh[0], sh[1]);
                if (ng < 4) {
                    mma_bf16(Y[2*ng+1], qh, sh[2], sh[3]);
                    mma_bf16(Y[2*ng+1], qh, sl4[2], sl4[3]);
                    mma_bf16(Y[2*ng+1], ql, sh[2], sh[3]);
                }
            }
        }
    }

    // ---- denominators (col 64 = tile 8, lanes with lane&3==0) ----
    if ((lane & 3) == 0) {
        float d0 = wv[8][0] + sl0 * Y1[8][0] + cl0 * Y2[8][0];
        float d1 = wv[8][2] + sl1 * Y1[8][2] + cl1 * Y2[8][2];
        sden[r0] = fmaxf(d0, EPSV);
        sden[r1] = fmaxf(d1, EPSV);
    }
    __syncthreads();
    const float inv0 = 1.0f / sden[r0];
    const float inv1 = 1.0f / sden[r1];

    // ---- combine + write attn as bf16 hi/lo ----
    const int rg0 = (cc * CHUNK + r0) * 2 + b;
    uint32_t* Ah0 = (uint32_t*)g_Ah;  // packed pairs, index (row*512+col)/2
    uint32_t* Al0 = (uint32_t*)g_Al;
#pragma unroll
    for (int t = 0; t < 8; t++) {
        int col = h * 64 + t * 8 + (lane & 3) * 2;
        float2 o0, o1;
        o0.x = (wv[t][0] + sl0 * Y1[t][0] + cl0 * Y2[t][0]) * inv0;
        o0.y = (wv[t][1] + sl0 * Y1[t][1] + cl0 * Y2[t][1]) * inv0;
        o1.x = (wv[t][2] + sl1 * Y1[t][2] + cl1 * Y2[t][2]) * inv1;
        o1.y = (wv[t][3] + sl1 * Y1[t][3] + cl1 * Y2[t][3]) * inv1;
        uint32_t lo, hi;
        size_t i0 = ((size_t)rg0 * E_DIM + col) >> 1;
        hi = split2(o0.x, o0.y, lo);
        Ah0[i0] = hi; Al0[i0] = lo;
        size_t i1 = ((size_t)(rg0 + 16) * E_DIM + col) >> 1;
        hi = split2(o1.x, o1.y, lo);
        Ah0[i1] = hi; Al0[i1] = lo;
    }
}

// ---------------------------------------------------------------------------
extern "C" void kernel_launch(void* const* d_in, const int* in_sizes, int n_in,
                              void* d_out, int out_size)
{
    const float* query = (const float*)d_in[0];
    const float* Wq = (const float*)d_in[1];
    const float* bq = (const float*)d_in[2];
    const float* Wk = (const float*)d_in[3];
    const float* bk = (const float*)d_in[4];
    const float* Wv = (const float*)d_in[5];
    const float* bv = (const float*)d_in[6];
    const float* Wo = (const float*)d_in[7];
    const float* bo = (const float*)d_in[8];
    float* out = (float*)d_out;

    cudaFuncSetAttribute(chunkattn_kernel,
                         cudaFuncAttributeMaxDynamicSharedMemorySize, CA_SMEM);
    cudaFuncSetAttribute(mma_qkv_kernel,
                         cudaFuncAttributeMaxDynamicSharedMemorySize, TC_SMEM);
    cudaFuncSetAttribute(mma_out_kernel,
                         cudaFuncAttributeMaxDynamicSharedMemorySize, TC_SMEM);

    convert_kernel<<<dim3(1024, 5), 256>>>(query, Wq, Wk, Wv, Wo);
    mma_qkv_kernel<<<dim3(16, 12), 256, TC_SMEM>>>(bq, bk, bv);
    chunksum_kernel<<<128, 256>>>();
    scan_kernel<<<dim3(16, 33), 256>>>();
    chunkattn_kernel<<<128, 256, CA_SMEM>>>();
    mma_out_kernel<<<dim3(16, 4), 256, TC_SMEM>>>(bo, out);
}